// round 7
// baseline (speedup 1.0000x reference)
#include <cuda_runtime.h>
#include <cuda_fp16.h>
#include <cstdint>
#include <math.h>

// Problem constants
#define BATCH 2
#define SEQ   1024
#define TOK   (BATCH*SEQ)      // 2048
#define DMODEL 1024
#define NHEAD 16
#define DK    64
#define FF    4096
#define NLAYER 4
#define LNEPS 1e-5f

#define H_ELEMS ((size_t)TOK * DMODEL)
#define AW_PER_LAYER ((size_t)BATCH * NHEAD * SEQ * SEQ)

// ------------------------- scratch (static device globals) -------------------------
__device__ float g_h  [TOK * DMODEL];
__device__ float g_q  [TOK * DMODEL];
__device__ float g_k  [TOK * DMODEL];
__device__ float g_v  [TOK * DMODEL];
__device__ float g_ctx[TOK * DMODEL];
__device__ float g_res[TOK * DMODEL];
__device__ float g_ff [TOK * FF];

// ------------------------------ fp16 helpers ----------------------------------------
__device__ __forceinline__ uint32_t pack_half2(float x, float y) {
    __half2 h = __floats2half2_rn(x, y);
    return *(uint32_t*)&h;
}

__device__ __forceinline__ void mma16816(float c[4], const uint32_t a[4], const uint32_t b[2]) {
    asm volatile(
        "mma.sync.aligned.m16n8k16.row.col.f32.f16.f16.f32 "
        "{%0,%1,%2,%3}, {%4,%5,%6,%7}, {%8,%9}, {%0,%1,%2,%3};"
        : "+f"(c[0]), "+f"(c[1]), "+f"(c[2]), "+f"(c[3])
        : "r"(a[0]), "r"(a[1]), "r"(a[2]), "r"(a[3]), "r"(b[0]), "r"(b[1]));
}

// ===================== fp16 mma.sync GEMM core (double-buffered) =====================
// C[M,N] = A[M,K] @ B[K,N] + bias (ReLU optional). 256 thr, BM=BN=128, BK=32.
// warp tile 64x32 (8 warps as 2(M) x 4(N)). One __syncthreads per K-chunk.
#define GBK  32
#define GBKP 40

template <int RELU>
__device__ __forceinline__ void gemm_core_f16(
    const float* __restrict__ A,
    const float* __restrict__ B,
    const float* __restrict__ bias,
    float* __restrict__ C,
    int N, int K)
{
    __shared__ __half As[2][128][GBKP];
    __shared__ __half Bs[2][128][GBKP];   // [n][k] (transposed from gmem [k][n])

    const int tid = threadIdx.x;
    const int m0 = blockIdx.y * 128;
    const int n0 = blockIdx.x * 128;
    A += (size_t)m0 * K;
    B += n0;
    C += (size_t)m0 * N + n0;
    bias += n0;

    float4 pa[4], pb[4];
    const int NC = K / GBK;

    auto loadG = [&](int c) {
        #pragma unroll
        for (int t = 0; t < 4; t++) {
            int i = tid + t * 256;
            int r = i >> 3, kg = (i & 7) * 4;
            pa[t] = *(const float4*)(A + (size_t)r * K + c * GBK + kg);
        }
        #pragma unroll
        for (int t = 0; t < 4; t++) {
            int i = tid + t * 256;
            int r = i >> 5, cc = (i & 31) * 4;
            pb[t] = *(const float4*)(B + (size_t)(c * GBK + r) * N + cc);
        }
    };
    auto storeS = [&](int buf) {
        #pragma unroll
        for (int t = 0; t < 4; t++) {
            int i = tid + t * 256;
            int r = i >> 3, kg = (i & 7) * 4;
            uint2 o = make_uint2(pack_half2(pa[t].x, pa[t].y), pack_half2(pa[t].z, pa[t].w));
            *(uint2*)&As[buf][r][kg] = o;
        }
        #pragma unroll
        for (int t = 0; t < 4; t++) {
            int i = tid + t * 256;
            int r = i >> 5, cc = (i & 31) * 4;
            Bs[buf][cc + 0][r] = __float2half_rn(pb[t].x);
            Bs[buf][cc + 1][r] = __float2half_rn(pb[t].y);
            Bs[buf][cc + 2][r] = __float2half_rn(pb[t].z);
            Bs[buf][cc + 3][r] = __float2half_rn(pb[t].w);
        }
    };

    const int w = tid >> 5, lane = tid & 31;
    const int wm = (w & 1) * 64, wn = (w >> 1) * 32;
    const int g = lane >> 2, tg = lane & 3;

    float acc[4][4][4];
    #pragma unroll
    for (int ms = 0; ms < 4; ms++)
        #pragma unroll
        for (int ns = 0; ns < 4; ns++)
            #pragma unroll
            for (int r = 0; r < 4; r++) acc[ms][ns][r] = 0.0f;

    loadG(0);
    storeS(0);
    if (NC > 1) loadG(1);
    __syncthreads();

    for (int c = 0; c < NC; c++) {
        int buf = c & 1;
        if (c + 1 < NC) storeS(buf ^ 1);
        if (c + 2 < NC) loadG(c + 2);

        #pragma unroll
        for (int ks = 0; ks < 2; ks++) {
            uint32_t af[4][4], bf[4][2];
            #pragma unroll
            for (int ms = 0; ms < 4; ms++) {
                int row = wm + ms * 16 + g;
                int col = ks * 16 + 2 * tg;
                af[ms][0] = *(uint32_t*)&As[buf][row][col];
                af[ms][1] = *(uint32_t*)&As[buf][row + 8][col];
                af[ms][2] = *(uint32_t*)&As[buf][row][col + 8];
                af[ms][3] = *(uint32_t*)&As[buf][row + 8][col + 8];
            }
            #pragma unroll
            for (int ns = 0; ns < 4; ns++) {
                int n = wn + ns * 8 + g;
                int col = ks * 16 + 2 * tg;
                bf[ns][0] = *(uint32_t*)&Bs[buf][n][col];
                bf[ns][1] = *(uint32_t*)&Bs[buf][n][col + 8];
            }
            #pragma unroll
            for (int ms = 0; ms < 4; ms++)
                #pragma unroll
                for (int ns = 0; ns < 4; ns++)
                    mma16816(acc[ms][ns], af[ms], bf[ns]);
        }
        __syncthreads();
    }

    #pragma unroll
    for (int ms = 0; ms < 4; ms++) {
        #pragma unroll
        for (int ns = 0; ns < 4; ns++) {
            int row = wm + ms * 16 + g;
            int col = wn + ns * 8 + tg * 2;
            float b0 = bias[col], b1 = bias[col + 1];
            float v0 = acc[ms][ns][0] + b0;
            float v1 = acc[ms][ns][1] + b1;
            float v2 = acc[ms][ns][2] + b0;
            float v3 = acc[ms][ns][3] + b1;
            if (RELU) {
                v0 = fmaxf(v0, 0.0f); v1 = fmaxf(v1, 0.0f);
                v2 = fmaxf(v2, 0.0f); v3 = fmaxf(v3, 0.0f);
            }
            *(float2*)&C[(size_t)row * N + col] = make_float2(v0, v1);
            *(float2*)&C[(size_t)(row + 8) * N + col] = make_float2(v2, v3);
        }
    }
}

struct QKV3 {
    const float* W[3];
    const float* b[3];
    float* o[3];
};

template <int RELU>
__global__ __launch_bounds__(256) void gemm_f16(const float* __restrict__ A,
                                                const float* __restrict__ B,
                                                const float* __restrict__ bias,
                                                float* __restrict__ C, int N, int K) {
    gemm_core_f16<RELU>(A, B, bias, C, N, K);
}

__global__ __launch_bounds__(256) void gemm_qkv_f16(const float* __restrict__ A, QKV3 p) {
    int z = blockIdx.z;
    gemm_core_f16<0>(A, p.W[z], p.b[z], p.o[z], DMODEL, DMODEL);
}

// ================= fused attention (fp16 operands, fp32 softmax/output) ==============
// grid (SEQ/128, BATCH*NHEAD), 256 threads. Two-pass softmax; P written once (fp32)
// to d_out and consumed from smem (fp16) for P@V.
// smem: Qs[128][72] q x dim | Ks[128][72] tok x dim | Vt[64][136] dim x tok |
//       Ps[128][136] q x tok | red[4][128] | mrow[128] | srow[128]
#define ATT_HALVES (128*72 + 128*72 + 64*136 + 128*136)
#define ATT_SMEM   (ATT_HALVES*2 + (4*128 + 128 + 128)*4)

__global__ __launch_bounds__(256) void attn_fused(const float* __restrict__ q,
                                                  const float* __restrict__ k,
                                                  const float* __restrict__ v,
                                                  float* __restrict__ aw,
                                                  float* __restrict__ ctx) {
    extern __shared__ char smc[];
    __half* Qs = (__half*)smc;             // [128][72]
    __half* Ks = Qs + 128 * 72;            // [128][72]
    __half* Vt = Ks + 128 * 72;            // [64][136]
    __half* Ps = Vt + 64 * 136;            // [128][136]
    float* red  = (float*)(Ps + 128 * 136);// [4][128]
    float* mrow = red + 4 * 128;
    float* srow = mrow + 128;

    const int tid = threadIdx.x;
    const int mt = blockIdx.x, bh = blockIdx.y;
    const int b = bh >> 4, hh = bh & 15;
    const float* qb = q + (size_t)(b * SEQ + mt * 128) * DMODEL + hh * DK;
    const float* kb = k + (size_t)b * SEQ * DMODEL + hh * DK;
    const float* vb = v + (size_t)b * SEQ * DMODEL + hh * DK;
    float* awb = aw + (size_t)bh * SEQ * SEQ + (size_t)(mt * 128) * SEQ;

    const int w = tid >> 5, lane = tid & 31, g = lane >> 2, tg = lane & 3;
    const int wm = (w & 1) * 64, wn = (w >> 1) * 32, wni = w >> 1;   // S tile
    const int wm2 = (w & 3) * 32, wn2 = (w >> 2) * 32;               // PV tile

    // ---- load Q tile once ----
    #pragma unroll
    for (int t = 0; t < 8; t++) {
        int i = tid + t * 256;
        int r = i >> 4, c = (i & 15) * 4;
        float4 x = *(const float4*)(qb + (size_t)r * DMODEL + c);
        *(uint2*)&Qs[r * 72 + c] = make_uint2(pack_half2(x.x, x.y), pack_half2(x.z, x.w));
    }
    if (tid < 128) { mrow[tid] = -INFINITY; srow[tid] = 0.0f; }
    __syncthreads();

    // =========================== PASS 1: row max & sum ==============================
    for (int kt = 0; kt < 8; kt++) {
        #pragma unroll
        for (int t = 0; t < 8; t++) {
            int i = tid + t * 256;
            int r = i >> 4, c = (i & 15) * 4;
            float4 x = *(const float4*)(kb + (size_t)(kt * 128 + r) * DMODEL + c);
            *(uint2*)&Ks[r * 72 + c] = make_uint2(pack_half2(x.x, x.y), pack_half2(x.z, x.w));
        }
        __syncthreads();

        float acc[4][4][4];
        #pragma unroll
        for (int ms = 0; ms < 4; ms++)
            #pragma unroll
            for (int ns = 0; ns < 4; ns++)
                #pragma unroll
                for (int r = 0; r < 4; r++) acc[ms][ns][r] = 0.0f;

        #pragma unroll
        for (int ks = 0; ks < 4; ks++) {
            uint32_t af[4][4], bf[4][2];
            #pragma unroll
            for (int ms = 0; ms < 4; ms++) {
                int row = wm + ms * 16 + g, col = ks * 16 + 2 * tg;
                af[ms][0] = *(uint32_t*)&Qs[row * 72 + col];
                af[ms][1] = *(uint32_t*)&Qs[(row + 8) * 72 + col];
                af[ms][2] = *(uint32_t*)&Qs[row * 72 + col + 8];
                af[ms][3] = *(uint32_t*)&Qs[(row + 8) * 72 + col + 8];
            }
            #pragma unroll
            for (int ns = 0; ns < 4; ns++) {
                int n = wn + ns * 8 + g, col = ks * 16 + 2 * tg;
                bf[ns][0] = *(uint32_t*)&Ks[n * 72 + col];
                bf[ns][1] = *(uint32_t*)&Ks[n * 72 + col + 8];
            }
            #pragma unroll
            for (int ms = 0; ms < 4; ms++)
                #pragma unroll
                for (int ns = 0; ns < 4; ns++)
                    mma16816(acc[ms][ns], af[ms], bf[ns]);
        }
        #pragma unroll
        for (int ms = 0; ms < 4; ms++)
            #pragma unroll
            for (int ns = 0; ns < 4; ns++)
                #pragma unroll
                for (int r = 0; r < 4; r++) acc[ms][ns][r] *= 0.125f;

        // row max of this tile
        #pragma unroll
        for (int ms = 0; ms < 4; ms++) {
            #pragma unroll
            for (int half = 0; half < 2; half++) {
                float rm = -INFINITY;
                #pragma unroll
                for (int ns = 0; ns < 4; ns++)
                    rm = fmaxf(rm, fmaxf(acc[ms][ns][half * 2], acc[ms][ns][half * 2 + 1]));
                rm = fmaxf(rm, __shfl_xor_sync(0xffffffffu, rm, 1));
                rm = fmaxf(rm, __shfl_xor_sync(0xffffffffu, rm, 2));
                if (tg == 0) red[wni * 128 + wm + ms * 16 + half * 8 + g] = rm;
            }
        }
        __syncthreads();
        if (tid < 128) {
            float tm = fmaxf(fmaxf(red[tid], red[128 + tid]),
                             fmaxf(red[256 + tid], red[384 + tid]));
            float mo = mrow[tid];
            float mn = fmaxf(mo, tm);
            srow[tid] *= expf(mo - mn);
            mrow[tid] = mn;
        }
        __syncthreads();
        // row sum of exp
        #pragma unroll
        for (int ms = 0; ms < 4; ms++) {
            #pragma unroll
            for (int half = 0; half < 2; half++) {
                int row = wm + ms * 16 + half * 8 + g;
                float mr = mrow[row];
                float rs = 0.0f;
                #pragma unroll
                for (int ns = 0; ns < 4; ns++)
                    rs += expf(acc[ms][ns][half * 2] - mr) + expf(acc[ms][ns][half * 2 + 1] - mr);
                rs += __shfl_xor_sync(0xffffffffu, rs, 1);
                rs += __shfl_xor_sync(0xffffffffu, rs, 2);
                if (tg == 0) red[wni * 128 + row] = rs;
            }
        }
        __syncthreads();
        if (tid < 128)
            srow[tid] += red[tid] + red[128 + tid] + red[256 + tid] + red[384 + tid];
        __syncthreads();
    }

    if (tid < 128) srow[tid] = 1.0f / srow[tid];
    __syncthreads();

    // ================== PASS 2: recompute S, write P, accumulate P@V ================
    float acc2[2][4][4];
    #pragma unroll
    for (int ms = 0; ms < 2; ms++)
        #pragma unroll
        for (int ns = 0; ns < 4; ns++)
            #pragma unroll
            for (int r = 0; r < 4; r++) acc2[ms][ns][r] = 0.0f;

    for (int kt = 0; kt < 8; kt++) {
        #pragma unroll
        for (int t = 0; t < 8; t++) {
            int i = tid + t * 256;
            int r = i >> 4, c = (i & 15) * 4;
            float4 x = *(const float4*)(kb + (size_t)(kt * 128 + r) * DMODEL + c);
            *(uint2*)&Ks[r * 72 + c] = make_uint2(pack_half2(x.x, x.y), pack_half2(x.z, x.w));
            float4 y = *(const float4*)(vb + (size_t)(kt * 128 + r) * DMODEL + c);
            Vt[(c + 0) * 136 + r] = __float2half_rn(y.x);
            Vt[(c + 1) * 136 + r] = __float2half_rn(y.y);
            Vt[(c + 2) * 136 + r] = __float2half_rn(y.z);
            Vt[(c + 3) * 136 + r] = __float2half_rn(y.w);
        }
        __syncthreads();

        float acc[4][4][4];
        #pragma unroll
        for (int ms = 0; ms < 4; ms++)
            #pragma unroll
            for (int ns = 0; ns < 4; ns++)
                #pragma unroll
                for (int r = 0; r < 4; r++) acc[ms][ns][r] = 0.0f;

        #pragma unroll
        for (int ks = 0; ks < 4; ks++) {
            uint32_t af[4][4], bf[4][2];
            #pragma unroll
            for (int ms = 0; ms < 4; ms++) {
                int row = wm + ms * 16 + g, col = ks * 16 + 2 * tg;
                af[ms][0] = *(uint32_t*)&Qs[row * 72 + col];
                af[ms][1] = *(uint32_t*)&Qs[(row + 8) * 72 + col];
                af[ms][2] = *(uint32_t*)&Qs[row * 72 + col + 8];
                af[ms][3] = *(uint32_t*)&Qs[(row + 8) * 72 + col + 8];
            }
            #pragma unroll
            for (int ns = 0; ns < 4; ns++) {
                int n = wn + ns * 8 + g, col = ks * 16 + 2 * tg;
                bf[ns][0] = *(uint32_t*)&Ks[n * 72 + col];
                bf[ns][1] = *(uint32_t*)&Ks[n * 72 + col + 8];
            }
            #pragma unroll
            for (int ms = 0; ms < 4; ms++)
                #pragma unroll
                for (int ns = 0; ns < 4; ns++)
                    mma16816(acc[ms][ns], af[ms], bf[ns]);
        }

        // P = exp(S*scale - m) * (1/sum) -> smem fp16 + gmem fp32
        #pragma unroll
        for (int ms = 0; ms < 4; ms++) {
            int row0 = wm + ms * 16 + g;
            int row1 = row0 + 8;
            float m0 = mrow[row0], s0 = srow[row0];
            float m1 = mrow[row1], s1 = srow[row1];
            #pragma unroll
            for (int ns = 0; ns < 4; ns++) {
                int col = wn + ns * 8 + tg * 2;
                float p0 = expf(acc[ms][ns][0] * 0.125f - m0) * s0;
                float p1 = expf(acc[ms][ns][1] * 0.125f - m0) * s0;
                float p2 = expf(acc[ms][ns][2] * 0.125f - m1) * s1;
                float p3 = expf(acc[ms][ns][3] * 0.125f - m1) * s1;
                *(uint32_t*)&Ps[row0 * 136 + col] = pack_half2(p0, p1);
                *(uint32_t*)&Ps[row1 * 136 + col] = pack_half2(p2, p3);
                *(float2*)&awb[(size_t)row0 * SEQ + kt * 128 + col] = make_float2(p0, p1);
                *(float2*)&awb[(size_t)row1 * SEQ + kt * 128 + col] = make_float2(p2, p3);
            }
        }
        __syncthreads();

        // ctx += P @ V   (A = Ps [q][tok], B = Vt [dim][tok])
        #pragma unroll
        for (int ks = 0; ks < 8; ks++) {
            uint32_t af[2][4], bf[4][2];
            #pragma unroll
            for (int ms = 0; ms < 2; ms++) {
                int row = wm2 + ms * 16 + g, col = ks * 16 + 2 * tg;
                af[ms][0] = *(uint32_t*)&Ps[row * 136 + col];
                af[ms][1] = *(uint32_t*)&Ps[(row + 8) * 136 + col];
                af[ms][2] = *(uint32_t*)&Ps[row * 136 + col + 8];
                af[ms][3] = *(uint32_t*)&Ps[(row + 8) * 136 + col + 8];
            }
            #pragma unroll
            for (int ns = 0; ns < 4; ns++) {
                int n = wn2 + ns * 8 + g, col = ks * 16 + 2 * tg;
                bf[ns][0] = *(uint32_t*)&Vt[n * 136 + col];
                bf[ns][1] = *(uint32_t*)&Vt[n * 136 + col + 8];
            }
            #pragma unroll
            for (int ms = 0; ms < 2; ms++)
                #pragma unroll
                for (int ns = 0; ns < 4; ns++)
                    mma16816(acc2[ms][ns], af[ms], bf[ns]);
        }
        __syncthreads();
    }

    // ---- write ctx tile ----
    float* cb = ctx + (size_t)(b * SEQ + mt * 128) * DMODEL + hh * DK;
    #pragma unroll
    for (int ms = 0; ms < 2; ms++) {
        #pragma unroll
        for (int ns = 0; ns < 4; ns++) {
            int row = wm2 + ms * 16 + g;
            int col = wn2 + ns * 8 + tg * 2;
            *(float2*)&cb[(size_t)row * DMODEL + col] =
                make_float2(acc2[ms][ns][0], acc2[ms][ns][1]);
            *(float2*)&cb[(size_t)(row + 8) * DMODEL + col] =
                make_float2(acc2[ms][ns][2], acc2[ms][ns][3]);
        }
    }
}

// ------------------------- embedding + positional encoding -------------------------
__global__ void embed_kernel(const int* __restrict__ ids, const float* __restrict__ emb,
                             float* __restrict__ h) {
    int token = blockIdx.x;
    int d = blockIdx.y * 256 + threadIdx.x;
    int s = token & (SEQ - 1);
    int id = ids[token];
    float c_even = (float)((d >> 1) << 1);
    float div = __expf(c_even * (-logf(10000.0f) / (float)DMODEL));
    float ang = (float)s * div;
    float pe = (d & 1) ? cosf(ang) : sinf(ang);
    h[(size_t)token * DMODEL + d] = emb[(size_t)id * DMODEL + d] * 32.0f + pe;
}

// ------------------------- fused residual-add + LayerNorm ---------------------------
__global__ void add_ln_kernel(const float* __restrict__ x, const float* __restrict__ r,
                              const float* __restrict__ g, const float* __restrict__ b,
                              float* __restrict__ out) {
    const size_t row = blockIdx.x;
    const int tid = threadIdx.x;
    __shared__ float red[256];
    __shared__ float s_mu, s_rinv;
    float v[4];
    float s = 0.0f;
    #pragma unroll
    for (int i = 0; i < 4; i++) {
        int c = tid + i * 256;
        v[i] = x[row * DMODEL + c] + r[row * DMODEL + c];
        s += v[i];
    }
    red[tid] = s; __syncthreads();
    for (int t = 128; t > 0; t >>= 1) { if (tid < t) red[tid] += red[tid + t]; __syncthreads(); }
    if (tid == 0) s_mu = red[0] * (1.0f / DMODEL);
    __syncthreads();
    float mu = s_mu;
    float sq = 0.0f;
    #pragma unroll
    for (int i = 0; i < 4; i++) { float d = v[i] - mu; sq += d * d; }
    red[tid] = sq; __syncthreads();
    for (int t = 128; t > 0; t >>= 1) { if (tid < t) red[tid] += red[tid + t]; __syncthreads(); }
    if (tid == 0) s_rinv = rsqrtf(red[0] * (1.0f / DMODEL) + LNEPS);
    __syncthreads();
    float rinv = s_rinv;
    #pragma unroll
    for (int i = 0; i < 4; i++) {
        int c = tid + i * 256;
        out[row * DMODEL + c] = (v[i] - mu) * rinv * g[c] + b[c];
    }
}

// ====================================================================================
extern "C" void kernel_launch(void* const* d_in, const int* in_sizes, int n_in,
                              void* d_out, int out_size) {
    const int*   ids  = (const int*)  d_in[0];
    const float* emb  = (const float*)d_in[1];
    const float* Wq   = (const float*)d_in[2];
    const float* bq   = (const float*)d_in[3];
    const float* Wk   = (const float*)d_in[4];
    const float* bk   = (const float*)d_in[5];
    const float* Wv   = (const float*)d_in[6];
    const float* bv   = (const float*)d_in[7];
    const float* Wo   = (const float*)d_in[8];
    const float* bo   = (const float*)d_in[9];
    const float* W1   = (const float*)d_in[10];
    const float* b1   = (const float*)d_in[11];
    const float* W2   = (const float*)d_in[12];
    const float* b2   = (const float*)d_in[13];
    const float* ln1g = (const float*)d_in[14];
    const float* ln1b = (const float*)d_in[15];
    const float* ln2g = (const float*)d_in[16];
    const float* ln2b = (const float*)d_in[17];

    float* out = (float*)d_out;

    float *h, *q, *k, *v, *ctx, *res, *ff;
    cudaGetSymbolAddress((void**)&h,   g_h);
    cudaGetSymbolAddress((void**)&q,   g_q);
    cudaGetSymbolAddress((void**)&k,   g_k);
    cudaGetSymbolAddress((void**)&v,   g_v);
    cudaGetSymbolAddress((void**)&ctx, g_ctx);
    cudaGetSymbolAddress((void**)&res, g_res);
    cudaGetSymbolAddress((void**)&ff,  g_ff);

    cudaFuncSetAttribute(attn_fused, cudaFuncAttributeMaxDynamicSharedMemorySize, ATT_SMEM);

    embed_kernel<<<dim3(TOK, DMODEL / 256), 256>>>(ids, emb, h);

    dim3 gDD(DMODEL / 128, TOK / 128);       // (8, 16)
    dim3 gDF(FF / 128, TOK / 128);           // (32, 16)
    dim3 gQKV(DMODEL / 128, TOK / 128, 3);   // (8, 16, 3)
    dim3 gFA(SEQ / 128, BATCH * NHEAD);      // (8, 32)

    for (int l = 0; l < NLAYER; l++) {
        const float* Wo_l = Wo + (size_t)l * DMODEL * DMODEL;
        const float* W1_l = W1 + (size_t)l * DMODEL * FF;
        const float* W2_l = W2 + (size_t)l * FF * DMODEL;

        float* aw = out + H_ELEMS + (size_t)l * AW_PER_LAYER;

        QKV3 p;
        p.W[0] = Wq + (size_t)l * DMODEL * DMODEL;
        p.W[1] = Wk + (size_t)l * DMODEL * DMODEL;
        p.W[2] = Wv + (size_t)l * DMODEL * DMODEL;
        p.b[0] = bq + (size_t)l * DMODEL;
        p.b[1] = bk + (size_t)l * DMODEL;
        p.b[2] = bv + (size_t)l * DMODEL;
        p.o[0] = q; p.o[1] = k; p.o[2] = v;

        gemm_qkv_f16<<<gQKV, 256>>>(h, p);

        attn_fused<<<gFA, 256, ATT_SMEM>>>(q, k, v, aw, ctx);

        gemm_f16<0><<<gDD, 256>>>(ctx, Wo_l, bo + (size_t)l * DMODEL, res, DMODEL, DMODEL);
        add_ln_kernel<<<TOK, 256>>>(h, res, ln1g + (size_t)l * DMODEL, ln1b + (size_t)l * DMODEL, h);

        gemm_f16<1><<<gDF, 256>>>(h, W1_l, b1 + (size_t)l * FF, ff, FF, DMODEL);
        gemm_f16<0><<<gDD, 256>>>(ff, W2_l, b2 + (size_t)l * DMODEL, res, DMODEL, FF);

        float* dst = (l == NLAYER - 1) ? out : h;
        add_ln_kernel<<<TOK, 256>>>(h, res, ln2g + (size_t)l * DMODEL, ln2b + (size_t)l * DMODEL, dst);
    }
}

// round 9
// speedup vs baseline: 2.0929x; 2.0929x over previous
#include <cuda_runtime.h>
#include <cuda_fp16.h>
#include <cstdint>
#include <math.h>

// Problem constants
#define BATCH 2
#define SEQ   1024
#define TOK   (BATCH*SEQ)      // 2048
#define DMODEL 1024
#define NHEAD 16
#define DK    64
#define FF    4096
#define NLAYER 4
#define LNEPS 1e-5f

#define H_ELEMS ((size_t)TOK * DMODEL)
#define AW_PER_LAYER ((size_t)BATCH * NHEAD * SEQ * SEQ)

// ------------------------- scratch (static device globals) -------------------------
__device__ float g_h  [TOK * DMODEL];
__device__ float g_q  [TOK * DMODEL];
__device__ float g_k  [TOK * DMODEL];
__device__ float g_v  [TOK * DMODEL];
__device__ float g_ctx[TOK * DMODEL];
__device__ float g_res[TOK * DMODEL];
__device__ float g_ff [TOK * FF];

// ------------------------------ fp16 / mma helpers ----------------------------------
__device__ __forceinline__ uint32_t pack_half2(float x, float y) {
    __half2 h = __floats2half2_rn(x, y);
    return *(uint32_t*)&h;
}
__device__ __forceinline__ uint32_t cvta_smem(const void* p) {
    return (uint32_t)__cvta_generic_to_shared(p);
}
__device__ __forceinline__ void mma16816(float c[4], const uint32_t a[4], const uint32_t b[2]) {
    asm volatile(
        "mma.sync.aligned.m16n8k16.row.col.f32.f16.f16.f32 "
        "{%0,%1,%2,%3}, {%4,%5,%6,%7}, {%8,%9}, {%0,%1,%2,%3};"
        : "+f"(c[0]), "+f"(c[1]), "+f"(c[2]), "+f"(c[3])
        : "r"(a[0]), "r"(a[1]), "r"(a[2]), "r"(a[3]), "r"(b[0]), "r"(b[1]));
}
__device__ __forceinline__ void ldsm_x4(uint32_t& r0, uint32_t& r1, uint32_t& r2, uint32_t& r3,
                                        uint32_t addr) {
    asm volatile("ldmatrix.sync.aligned.m8n8.x4.shared.b16 {%0,%1,%2,%3}, [%4];"
                 : "=r"(r0), "=r"(r1), "=r"(r2), "=r"(r3) : "r"(addr));
}
__device__ __forceinline__ void ldsm_x4_t(uint32_t& r0, uint32_t& r1, uint32_t& r2, uint32_t& r3,
                                          uint32_t addr) {
    asm volatile("ldmatrix.sync.aligned.m8n8.x4.trans.shared.b16 {%0,%1,%2,%3}, [%4];"
                 : "=r"(r0), "=r"(r1), "=r"(r2), "=r"(r3) : "r"(addr));
}

// ===================== fp16 ldmatrix GEMM core (double-buffered, 1 sync) =============
// C[M,N] = A[M,K] @ B[K,N] + bias (ReLU optional). 256 thr, BM=BN=128, BK=32.
// 8 warps as 2(M) x 4(N), warp tile 64x32. A smem [m][k] (pad 40), B smem [k][n] (pad 136).
// Loop order: storeS(next) -> loadG(next+1) -> mma(cur) -> sync.
#define GBK  32
#define GBKP 40
#define GBNP 136

template <int RELU>
__device__ __forceinline__ void gemm_core_f16(
    const float* __restrict__ A,
    const float* __restrict__ B,
    const float* __restrict__ bias,
    float* __restrict__ C,
    int N, int K)
{
    __shared__ __half As[2][128 * GBKP];
    __shared__ __half Bs[2][GBK * GBNP];

    const int tid = threadIdx.x;
    const int m0 = blockIdx.y * 128;
    const int n0 = blockIdx.x * 128;
    A += (size_t)m0 * K;
    B += n0;
    C += (size_t)m0 * N + n0;
    bias += n0;

    float4 pa[4], pb[4];
    const int NC = K / GBK;

    auto loadG = [&](int c) {
        #pragma unroll
        for (int t = 0; t < 4; t++) {
            int i = tid + t * 256;
            int r = i >> 3, kg = (i & 7) * 4;
            pa[t] = *(const float4*)(A + (size_t)r * K + c * GBK + kg);
        }
        #pragma unroll
        for (int t = 0; t < 4; t++) {
            int i = tid + t * 256;
            int r = i >> 5, cc = (i & 31) * 4;
            pb[t] = *(const float4*)(B + (size_t)(c * GBK + r) * N + cc);
        }
    };
    auto storeS = [&](int buf) {
        #pragma unroll
        for (int t = 0; t < 4; t++) {
            int i = tid + t * 256;
            int r = i >> 3, kg = (i & 7) * 4;
            *(uint2*)&As[buf][r * GBKP + kg] =
                make_uint2(pack_half2(pa[t].x, pa[t].y), pack_half2(pa[t].z, pa[t].w));
        }
        #pragma unroll
        for (int t = 0; t < 4; t++) {
            int i = tid + t * 256;
            int r = i >> 5, cc = (i & 31) * 4;
            *(uint2*)&Bs[buf][r * GBNP + cc] =
                make_uint2(pack_half2(pb[t].x, pb[t].y), pack_half2(pb[t].z, pb[t].w));
        }
    };

    const int w = tid >> 5, lane = tid & 31;
    const int wm = (w & 1) * 64, wn = (w >> 1) * 32;
    const int g = lane >> 2, tg = lane & 3;
    const int lr = lane & 15;                 // ldmatrix row-within-16
    const int lc = (lane >> 4) * 8;           // ldmatrix col-group

    float acc[4][4][4];
    #pragma unroll
    for (int ms = 0; ms < 4; ms++)
        #pragma unroll
        for (int ns = 0; ns < 4; ns++)
            #pragma unroll
            for (int r = 0; r < 4; r++) acc[ms][ns][r] = 0.0f;

    loadG(0);
    storeS(0);
    if (NC > 1) loadG(1);
    __syncthreads();

    for (int c = 0; c < NC; c++) {
        int buf = c & 1;
        if (c + 1 < NC) storeS(buf ^ 1);   // registers hold chunk c+1
        if (c + 2 < NC) loadG(c + 2);      // refill registers AFTER storing

        const uint32_t baseA = cvta_smem(&As[buf][0]);
        const uint32_t baseB = cvta_smem(&Bs[buf][0]);
        #pragma unroll
        for (int ks = 0; ks < 2; ks++) {
            uint32_t af[4][4], bf[4][2];
            #pragma unroll
            for (int ms = 0; ms < 4; ms++) {
                uint32_t ad = baseA + 2u * ((wm + ms * 16 + lr) * GBKP + ks * 16 + lc);
                ldsm_x4(af[ms][0], af[ms][1], af[ms][2], af[ms][3], ad);
            }
            #pragma unroll
            for (int p = 0; p < 2; p++) {
                int row = ks * 16 + lr;
                int col = wn + p * 16 + lc;
                uint32_t ad = baseB + 2u * (row * GBNP + col);
                ldsm_x4_t(bf[2 * p][0], bf[2 * p][1], bf[2 * p + 1][0], bf[2 * p + 1][1], ad);
            }
            #pragma unroll
            for (int ms = 0; ms < 4; ms++)
                #pragma unroll
                for (int ns = 0; ns < 4; ns++)
                    mma16816(acc[ms][ns], af[ms], bf[ns]);
        }
        __syncthreads();
    }

    #pragma unroll
    for (int ms = 0; ms < 4; ms++) {
        #pragma unroll
        for (int ns = 0; ns < 4; ns++) {
            int row = wm + ms * 16 + g;
            int col = wn + ns * 8 + tg * 2;
            float b0 = bias[col], b1 = bias[col + 1];
            float v0 = acc[ms][ns][0] + b0;
            float v1 = acc[ms][ns][1] + b1;
            float v2 = acc[ms][ns][2] + b0;
            float v3 = acc[ms][ns][3] + b1;
            if (RELU) {
                v0 = fmaxf(v0, 0.0f); v1 = fmaxf(v1, 0.0f);
                v2 = fmaxf(v2, 0.0f); v3 = fmaxf(v3, 0.0f);
            }
            *(float2*)&C[(size_t)row * N + col] = make_float2(v0, v1);
            *(float2*)&C[(size_t)(row + 8) * N + col] = make_float2(v2, v3);
        }
    }
}

struct QKV3 {
    const float* W[3];
    const float* b[3];
    float* o[3];
};

template <int RELU>
__global__ __launch_bounds__(256) void gemm_f16(const float* __restrict__ A,
                                                const float* __restrict__ B,
                                                const float* __restrict__ bias,
                                                float* __restrict__ C, int N, int K) {
    gemm_core_f16<RELU>(A, B, bias, C, N, K);
}

__global__ __launch_bounds__(256) void gemm_qkv_f16(const float* __restrict__ A, QKV3 p) {
    int z = blockIdx.z;
    gemm_core_f16<0>(A, p.W[z], p.b[z], p.o[z], DMODEL, DMODEL);
}

// ================= fused attention (fp16 + ldmatrix, fp32 softmax/output) ============
// grid (SEQ/128, BATCH*NHEAD), 256 threads. Two-pass softmax; P written once (fp32)
// to d_out and consumed from smem (fp16) for P@V.
#define ATT_HALVES (128*72 + 128*72 + 128*72 + 128*136)
#define ATT_SMEM   (ATT_HALVES*2 + (4*128 + 128 + 128)*4)

__global__ __launch_bounds__(256) void attn_fused(const float* __restrict__ q,
                                                  const float* __restrict__ k,
                                                  const float* __restrict__ v,
                                                  float* __restrict__ aw,
                                                  float* __restrict__ ctx) {
    extern __shared__ char smc[];
    __half* Qs = (__half*)smc;              // [128][72]
    __half* Ks = Qs + 128 * 72;             // [128][72]
    __half* Vs = Ks + 128 * 72;             // [128][72]
    __half* Ps = Vs + 128 * 72;             // [128][136]
    float* red  = (float*)(Ps + 128 * 136); // [4][128]
    float* mrow = red + 4 * 128;
    float* srow = mrow + 128;

    const int tid = threadIdx.x;
    const int mt = blockIdx.x, bh = blockIdx.y;
    const int b = bh >> 4, hh = bh & 15;
    const float* qb = q + (size_t)(b * SEQ + mt * 128) * DMODEL + hh * DK;
    const float* kb = k + (size_t)b * SEQ * DMODEL + hh * DK;
    const float* vb = v + (size_t)b * SEQ * DMODEL + hh * DK;
    float* awb = aw + (size_t)bh * SEQ * SEQ + (size_t)(mt * 128) * SEQ;

    const int w = tid >> 5, lane = tid & 31, g = lane >> 2, tg = lane & 3;
    const int wm = (w & 1) * 64, wn = (w >> 1) * 32, wni = w >> 1;   // S tile 2x4 warps
    const int wm2 = (w & 3) * 32, wn2 = (w >> 2) * 32;               // PV tile 4x2 warps
    const int lr = lane & 15;
    const int lc = (lane >> 4) * 8;
    const int nB = (lane & 7) + ((lane >> 4) << 3);   // non-trans B: n row
    const int kB = ((lane >> 3) & 1) * 8;             // non-trans B: k col group

    const uint32_t uQs = cvta_smem(Qs);
    const uint32_t uKs = cvta_smem(Ks);
    const uint32_t uVs = cvta_smem(Vs);
    const uint32_t uPs = cvta_smem(Ps);

    // ---- load Q tile once ----
    #pragma unroll
    for (int t = 0; t < 8; t++) {
        int i = tid + t * 256;
        int r = i >> 4, c = (i & 15) * 4;
        float4 x = *(const float4*)(qb + (size_t)r * DMODEL + c);
        *(uint2*)&Qs[r * 72 + c] = make_uint2(pack_half2(x.x, x.y), pack_half2(x.z, x.w));
    }
    if (tid < 128) { mrow[tid] = -INFINITY; srow[tid] = 0.0f; }
    __syncthreads();

    // =========================== PASS 1: row max & sum ==============================
    for (int kt = 0; kt < 8; kt++) {
        #pragma unroll
        for (int t = 0; t < 8; t++) {
            int i = tid + t * 256;
            int r = i >> 4, c = (i & 15) * 4;
            float4 x = *(const float4*)(kb + (size_t)(kt * 128 + r) * DMODEL + c);
            *(uint2*)&Ks[r * 72 + c] = make_uint2(pack_half2(x.x, x.y), pack_half2(x.z, x.w));
        }
        __syncthreads();

        float acc[4][4][4];
        #pragma unroll
        for (int ms = 0; ms < 4; ms++)
            #pragma unroll
            for (int ns = 0; ns < 4; ns++)
                #pragma unroll
                for (int r = 0; r < 4; r++) acc[ms][ns][r] = 0.0f;

        #pragma unroll
        for (int ks = 0; ks < 4; ks++) {
            uint32_t af[4][4], bf[4][2];
            #pragma unroll
            for (int ms = 0; ms < 4; ms++) {
                uint32_t ad = uQs + 2u * ((wm + ms * 16 + lr) * 72 + ks * 16 + lc);
                ldsm_x4(af[ms][0], af[ms][1], af[ms][2], af[ms][3], ad);
            }
            #pragma unroll
            for (int p = 0; p < 2; p++) {
                int n = wn + p * 16 + nB;
                uint32_t ad = uKs + 2u * (n * 72 + ks * 16 + kB);
                ldsm_x4(bf[2 * p][0], bf[2 * p][1], bf[2 * p + 1][0], bf[2 * p + 1][1], ad);
            }
            #pragma unroll
            for (int ms = 0; ms < 4; ms++)
                #pragma unroll
                for (int ns = 0; ns < 4; ns++)
                    mma16816(acc[ms][ns], af[ms], bf[ns]);
        }
        #pragma unroll
        for (int ms = 0; ms < 4; ms++)
            #pragma unroll
            for (int ns = 0; ns < 4; ns++)
                #pragma unroll
                for (int r = 0; r < 4; r++) acc[ms][ns][r] *= 0.125f;

        // row max of this tile
        #pragma unroll
        for (int ms = 0; ms < 4; ms++) {
            #pragma unroll
            for (int half = 0; half < 2; half++) {
                float rm = -INFINITY;
                #pragma unroll
                for (int ns = 0; ns < 4; ns++)
                    rm = fmaxf(rm, fmaxf(acc[ms][ns][half * 2], acc[ms][ns][half * 2 + 1]));
                rm = fmaxf(rm, __shfl_xor_sync(0xffffffffu, rm, 1));
                rm = fmaxf(rm, __shfl_xor_sync(0xffffffffu, rm, 2));
                if (tg == 0) red[wni * 128 + wm + ms * 16 + half * 8 + g] = rm;
            }
        }
        __syncthreads();
        if (tid < 128) {
            float tm = fmaxf(fmaxf(red[tid], red[128 + tid]),
                             fmaxf(red[256 + tid], red[384 + tid]));
            float mo = mrow[tid];
            float mn = fmaxf(mo, tm);
            srow[tid] *= expf(mo - mn);
            mrow[tid] = mn;
        }
        __syncthreads();
        // row sum of exp
        #pragma unroll
        for (int ms = 0; ms < 4; ms++) {
            #pragma unroll
            for (int half = 0; half < 2; half++) {
                int row = wm + ms * 16 + half * 8 + g;
                float mr = mrow[row];
                float rs = 0.0f;
                #pragma unroll
                for (int ns = 0; ns < 4; ns++)
                    rs += expf(acc[ms][ns][half * 2] - mr) + expf(acc[ms][ns][half * 2 + 1] - mr);
                rs += __shfl_xor_sync(0xffffffffu, rs, 1);
                rs += __shfl_xor_sync(0xffffffffu, rs, 2);
                if (tg == 0) red[wni * 128 + row] = rs;
            }
        }
        __syncthreads();
        if (tid < 128)
            srow[tid] += red[tid] + red[128 + tid] + red[256 + tid] + red[384 + tid];
        __syncthreads();
    }

    if (tid < 128) srow[tid] = 1.0f / srow[tid];
    __syncthreads();

    // ================== PASS 2: recompute S, write P, accumulate P@V ================
    float acc2[2][4][4];
    #pragma unroll
    for (int ms = 0; ms < 2; ms++)
        #pragma unroll
        for (int ns = 0; ns < 4; ns++)
            #pragma unroll
            for (int r = 0; r < 4; r++) acc2[ms][ns][r] = 0.0f;

    for (int kt = 0; kt < 8; kt++) {
        #pragma unroll
        for (int t = 0; t < 8; t++) {
            int i = tid + t * 256;
            int r = i >> 4, c = (i & 15) * 4;
            float4 x = *(const float4*)(kb + (size_t)(kt * 128 + r) * DMODEL + c);
            *(uint2*)&Ks[r * 72 + c] = make_uint2(pack_half2(x.x, x.y), pack_half2(x.z, x.w));
            float4 y = *(const float4*)(vb + (size_t)(kt * 128 + r) * DMODEL + c);
            *(uint2*)&Vs[r * 72 + c] = make_uint2(pack_half2(y.x, y.y), pack_half2(y.z, y.w));
        }
        __syncthreads();

        float acc[4][4][4];
        #pragma unroll
        for (int ms = 0; ms < 4; ms++)
            #pragma unroll
            for (int ns = 0; ns < 4; ns++)
                #pragma unroll
                for (int r = 0; r < 4; r++) acc[ms][ns][r] = 0.0f;

        #pragma unroll
        for (int ks = 0; ks < 4; ks++) {
            uint32_t af[4][4], bf[4][2];
            #pragma unroll
            for (int ms = 0; ms < 4; ms++) {
                uint32_t ad = uQs + 2u * ((wm + ms * 16 + lr) * 72 + ks * 16 + lc);
                ldsm_x4(af[ms][0], af[ms][1], af[ms][2], af[ms][3], ad);
            }
            #pragma unroll
            for (int p = 0; p < 2; p++) {
                int n = wn + p * 16 + nB;
                uint32_t ad = uKs + 2u * (n * 72 + ks * 16 + kB);
                ldsm_x4(bf[2 * p][0], bf[2 * p][1], bf[2 * p + 1][0], bf[2 * p + 1][1], ad);
            }
            #pragma unroll
            for (int ms = 0; ms < 4; ms++)
                #pragma unroll
                for (int ns = 0; ns < 4; ns++)
                    mma16816(acc[ms][ns], af[ms], bf[ns]);
        }

        // P = exp(S*scale - m) * (1/sum) -> smem fp16 + gmem fp32
        #pragma unroll
        for (int ms = 0; ms < 4; ms++) {
            int row0 = wm + ms * 16 + g;
            int row1 = row0 + 8;
            float m0 = mrow[row0], s0 = srow[row0];
            float m1 = mrow[row1], s1 = srow[row1];
            #pragma unroll
            for (int ns = 0; ns < 4; ns++) {
                int col = wn + ns * 8 + tg * 2;
                float p0 = expf(acc[ms][ns][0] * 0.125f - m0) * s0;
                float p1 = expf(acc[ms][ns][1] * 0.125f - m0) * s0;
                float p2 = expf(acc[ms][ns][2] * 0.125f - m1) * s1;
                float p3 = expf(acc[ms][ns][3] * 0.125f - m1) * s1;
                *(uint32_t*)&Ps[row0 * 136 + col] = pack_half2(p0, p1);
                *(uint32_t*)&Ps[row1 * 136 + col] = pack_half2(p2, p3);
                *(float2*)&awb[(size_t)row0 * SEQ + kt * 128 + col] = make_float2(p0, p1);
                *(float2*)&awb[(size_t)row1 * SEQ + kt * 128 + col] = make_float2(p2, p3);
            }
        }
        __syncthreads();

        // ctx += P @ V   (A = Ps [q][tok], B = Vs [tok][dim] via trans ldmatrix)
        #pragma unroll
        for (int ks = 0; ks < 8; ks++) {
            uint32_t af[2][4], bf[4][2];
            #pragma unroll
            for (int ms = 0; ms < 2; ms++) {
                uint32_t ad = uPs + 2u * ((wm2 + ms * 16 + lr) * 136 + ks * 16 + lc);
                ldsm_x4(af[ms][0], af[ms][1], af[ms][2], af[ms][3], ad);
            }
            #pragma unroll
            for (int p = 0; p < 2; p++) {
                int row = ks * 16 + lr;
                int col = wn2 + p * 16 + lc;
                uint32_t ad = uVs + 2u * (row * 72 + col);
                ldsm_x4_t(bf[2 * p][0], bf[2 * p][1], bf[2 * p + 1][0], bf[2 * p + 1][1], ad);
            }
            #pragma unroll
            for (int ms = 0; ms < 2; ms++)
                #pragma unroll
                for (int ns = 0; ns < 4; ns++)
                    mma16816(acc2[ms][ns], af[ms], bf[ns]);
        }
        __syncthreads();
    }

    // ---- write ctx tile ----
    float* cb = ctx + (size_t)(b * SEQ + mt * 128) * DMODEL + hh * DK;
    #pragma unroll
    for (int ms = 0; ms < 2; ms++) {
        #pragma unroll
        for (int ns = 0; ns < 4; ns++) {
            int row = wm2 + ms * 16 + g;
            int col = wn2 + ns * 8 + tg * 2;
            *(float2*)&cb[(size_t)row * DMODEL + col] =
                make_float2(acc2[ms][ns][0], acc2[ms][ns][1]);
            *(float2*)&cb[(size_t)(row + 8) * DMODEL + col] =
                make_float2(acc2[ms][ns][2], acc2[ms][ns][3]);
        }
    }
}

// ------------------------- embedding + positional encoding -------------------------
__global__ void embed_kernel(const int* __restrict__ ids, const float* __restrict__ emb,
                             float* __restrict__ h) {
    int token = blockIdx.x;
    int d = blockIdx.y * 256 + threadIdx.x;
    int s = token & (SEQ - 1);
    int id = ids[token];
    float c_even = (float)((d >> 1) << 1);
    float div = __expf(c_even * (-logf(10000.0f) / (float)DMODEL));
    float ang = (float)s * div;
    float pe = (d & 1) ? cosf(ang) : sinf(ang);
    h[(size_t)token * DMODEL + d] = emb[(size_t)id * DMODEL + d] * 32.0f + pe;
}

// ------------------------- fused residual-add + LayerNorm ---------------------------
__global__ void add_ln_kernel(const float* __restrict__ x, const float* __restrict__ r,
                              const float* __restrict__ g, const float* __restrict__ b,
                              float* __restrict__ out) {
    const size_t row = blockIdx.x;
    const int tid = threadIdx.x;
    __shared__ float red[256];
    __shared__ float s_mu, s_rinv;
    float v[4];
    float s = 0.0f;
    #pragma unroll
    for (int i = 0; i < 4; i++) {
        int c = tid + i * 256;
        v[i] = x[row * DMODEL + c] + r[row * DMODEL + c];
        s += v[i];
    }
    red[tid] = s; __syncthreads();
    for (int t = 128; t > 0; t >>= 1) { if (tid < t) red[tid] += red[tid + t]; __syncthreads(); }
    if (tid == 0) s_mu = red[0] * (1.0f / DMODEL);
    __syncthreads();
    float mu = s_mu;
    float sq = 0.0f;
    #pragma unroll
    for (int i = 0; i < 4; i++) { float d = v[i] - mu; sq += d * d; }
    red[tid] = sq; __syncthreads();
    for (int t = 128; t > 0; t >>= 1) { if (tid < t) red[tid] += red[tid + t]; __syncthreads(); }
    if (tid == 0) s_rinv = rsqrtf(red[0] * (1.0f / DMODEL) + LNEPS);
    __syncthreads();
    float rinv = s_rinv;
    #pragma unroll
    for (int i = 0; i < 4; i++) {
        int c = tid + i * 256;
        out[row * DMODEL + c] = (v[i] - mu) * rinv * g[c] + b[c];
    }
}

// ====================================================================================
extern "C" void kernel_launch(void* const* d_in, const int* in_sizes, int n_in,
                              void* d_out, int out_size) {
    const int*   ids  = (const int*)  d_in[0];
    const float* emb  = (const float*)d_in[1];
    const float* Wq   = (const float*)d_in[2];
    const float* bq   = (const float*)d_in[3];
    const float* Wk   = (const float*)d_in[4];
    const float* bk   = (const float*)d_in[5];
    const float* Wv   = (const float*)d_in[6];
    const float* bv   = (const float*)d_in[7];
    const float* Wo   = (const float*)d_in[8];
    const float* bo   = (const float*)d_in[9];
    const float* W1   = (const float*)d_in[10];
    const float* b1   = (const float*)d_in[11];
    const float* W2   = (const float*)d_in[12];
    const float* b2   = (const float*)d_in[13];
    const float* ln1g = (const float*)d_in[14];
    const float* ln1b = (const float*)d_in[15];
    const float* ln2g = (const float*)d_in[16];
    const float* ln2b = (const float*)d_in[17];

    float* out = (float*)d_out;

    float *h, *q, *k, *v, *ctx, *res, *ff;
    cudaGetSymbolAddress((void**)&h,   g_h);
    cudaGetSymbolAddress((void**)&q,   g_q);
    cudaGetSymbolAddress((void**)&k,   g_k);
    cudaGetSymbolAddress((void**)&v,   g_v);
    cudaGetSymbolAddress((void**)&ctx, g_ctx);
    cudaGetSymbolAddress((void**)&res, g_res);
    cudaGetSymbolAddress((void**)&ff,  g_ff);

    cudaFuncSetAttribute(attn_fused, cudaFuncAttributeMaxDynamicSharedMemorySize, ATT_SMEM);

    embed_kernel<<<dim3(TOK, DMODEL / 256), 256>>>(ids, emb, h);

    dim3 gDD(DMODEL / 128, TOK / 128);       // (8, 16)
    dim3 gDF(FF / 128, TOK / 128);           // (32, 16)
    dim3 gQKV(DMODEL / 128, TOK / 128, 3);   // (8, 16, 3)
    dim3 gFA(SEQ / 128, BATCH * NHEAD);      // (8, 32)

    for (int l = 0; l < NLAYER; l++) {
        const float* Wo_l = Wo + (size_t)l * DMODEL * DMODEL;
        const float* W1_l = W1 + (size_t)l * DMODEL * FF;
        const float* W2_l = W2 + (size_t)l * FF * DMODEL;

        float* aw = out + H_ELEMS + (size_t)l * AW_PER_LAYER;

        QKV3 p;
        p.W[0] = Wq + (size_t)l * DMODEL * DMODEL;
        p.W[1] = Wk + (size_t)l * DMODEL * DMODEL;
        p.W[2] = Wv + (size_t)l * DMODEL * DMODEL;
        p.b[0] = bq + (size_t)l * DMODEL;
        p.b[1] = bk + (size_t)l * DMODEL;
        p.b[2] = bv + (size_t)l * DMODEL;
        p.o[0] = q; p.o[1] = k; p.o[2] = v;

        gemm_qkv_f16<<<gQKV, 256>>>(h, p);

        attn_fused<<<gFA, 256, ATT_SMEM>>>(q, k, v, aw, ctx);

        gemm_f16<0><<<gDD, 256>>>(ctx, Wo_l, bo + (size_t)l * DMODEL, res, DMODEL, DMODEL);
        add_ln_kernel<<<TOK, 256>>>(h, res, ln1g + (size_t)l * DMODEL, ln1b + (size_t)l * DMODEL, h);

        gemm_f16<1><<<gDF, 256>>>(h, W1_l, b1 + (size_t)l * FF, ff, FF, DMODEL);
        gemm_f16<0><<<gDD, 256>>>(ff, W2_l, b2 + (size_t)l * DMODEL, res, DMODEL, FF);

        float* dst = (l == NLAYER - 1) ? out : h;
        add_ln_kernel<<<TOK, 256>>>(h, res, ln2g + (size_t)l * DMODEL, ln2b + (size_t)l * DMODEL, dst);
    }
}